// round 6
// baseline (speedup 1.0000x reference)
#include <cuda_runtime.h>
#include <cuda_bf16.h>
#include <cstdint>

#define NNODES   50000
#define ETOT_MAX 900000
#define HID      256
#define NHEAD    8
#define SCAN_NB  196          // 196*256 = 50176 >= NNODES

// ================= scratch (static device globals) =================
__device__ int   g_rowptr[NNODES + 1];
__device__ int   g_cursor[NNODES];
__device__ int   g_scantmp[NNODES];
__device__ int   g_bsum[256];
__device__ int   g_srcs[ETOT_MAX];
__device__ __align__(16) float g_h[NNODES * HID];    // transformed features (current layer)
__device__ __align__(16) float g_x1[NNODES * HID];   // layer-1 output
__device__ float g_als[NNODES * NHEAD];
__device__ float g_ald[NNODES * NHEAD];
// bf16 hi/lo split weights, stored [n][k]
__device__ __align__(16) __nv_bfloat16 g_b1hi[HID * 128];
__device__ __align__(16) __nv_bfloat16 g_b1lo[HID * 128];
__device__ __align__(16) __nv_bfloat16 g_b2hi[HID * HID];
__device__ __align__(16) __nv_bfloat16 g_b2lo[HID * HID];

// ================= CSR build =================
__global__ void zero_counts_kernel() {
    int i = blockIdx.x * blockDim.x + threadIdx.x;
    if (i <= NNODES) g_rowptr[i] = 0;
}

__global__ void hist_kernel(const int* __restrict__ dst, int etot) {
    int i = blockIdx.x * blockDim.x + threadIdx.x;
    int n4 = etot >> 2;
    if (i < n4) {
        int4 d = ((const int4*)dst)[i];
        atomicAdd(&g_rowptr[d.x], 1);
        atomicAdd(&g_rowptr[d.y], 1);
        atomicAdd(&g_rowptr[d.z], 1);
        atomicAdd(&g_rowptr[d.w], 1);
    }
    int rem = etot - n4 * 4;
    if (i < rem) atomicAdd(&g_rowptr[dst[n4 * 4 + i]], 1);
}

// two-level scan
__global__ void scan_local_kernel() {
    int t = threadIdx.x, i = blockIdx.x * 256 + t;
    int lane = t & 31, wid = t >> 5;
    int val = (i < NNODES) ? g_rowptr[i] : 0;
    int x = val;
    #pragma unroll
    for (int o = 1; o < 32; o <<= 1) {
        int y = __shfl_up_sync(0xffffffffu, x, o);
        if (lane >= o) x += y;
    }
    __shared__ int wsum[8];
    if (lane == 31) wsum[wid] = x;
    __syncthreads();
    if (t < 8) {
        int s = wsum[t];
        #pragma unroll
        for (int o = 1; o < 8; o <<= 1) {
            int y = __shfl_up_sync(0xffu, s, o);
            if (t >= o) s += y;
        }
        wsum[t] = s;
    }
    __syncthreads();
    int incl = x + (wid ? wsum[wid - 1] : 0);
    if (i < NNODES) g_scantmp[i] = incl - val;
    if (t == 255) g_bsum[blockIdx.x] = incl;
}

__global__ void scan_bsums_kernel() {
    int t = threadIdx.x;
    int lane = t & 31, wid = t >> 5;
    int val = (t < SCAN_NB) ? g_bsum[t] : 0;
    int x = val;
    #pragma unroll
    for (int o = 1; o < 32; o <<= 1) {
        int y = __shfl_up_sync(0xffffffffu, x, o);
        if (lane >= o) x += y;
    }
    __shared__ int wsum[8];
    if (lane == 31) wsum[wid] = x;
    __syncthreads();
    if (t < 8) {
        int s = wsum[t];
        #pragma unroll
        for (int o = 1; o < 8; o <<= 1) {
            int y = __shfl_up_sync(0xffu, s, o);
            if (t >= o) s += y;
        }
        wsum[t] = s;
    }
    __syncthreads();
    int incl = x + (wid ? wsum[wid - 1] : 0);
    if (t < SCAN_NB) g_bsum[t] = incl - val;
    if (t == 255) g_rowptr[NNODES] = incl;
}

__global__ void scan_add_kernel() {
    int i = blockIdx.x * 256 + threadIdx.x;
    if (i < NNODES) {
        int e = g_scantmp[i] + g_bsum[blockIdx.x];
        g_rowptr[i] = e;
        g_cursor[i] = e;
    }
}

__global__ void scatter_kernel(const int* __restrict__ src,
                               const int* __restrict__ dst, int etot) {
    int i = blockIdx.x * blockDim.x + threadIdx.x;
    int n4 = etot >> 2;
    if (i < n4) {
        int4 s = ((const int4*)src)[i];
        int4 d = ((const int4*)dst)[i];
        g_srcs[atomicAdd(&g_cursor[d.x], 1)] = s.x;
        g_srcs[atomicAdd(&g_cursor[d.y], 1)] = s.y;
        g_srcs[atomicAdd(&g_cursor[d.z], 1)] = s.z;
        g_srcs[atomicAdd(&g_cursor[d.w], 1)] = s.w;
    }
    int rem = etot - n4 * 4;
    if (i < rem) {
        int j = n4 * 4 + i;
        g_srcs[atomicAdd(&g_cursor[dst[j]], 1)] = src[j];
    }
}

// ================= weight fp32 -> bf16 hi/lo split (both layers, one kernel) =================
__global__ void convW_kernel(const float* __restrict__ W1, const float* __restrict__ W2) {
    int i = blockIdx.x * blockDim.x + threadIdx.x;
    const int n1 = 128 * HID;
    if (i < n1) {                       // W1 [128][256]
        int k = i / HID, n = i - k * HID;
        float x = W1[i];
        __nv_bfloat16 h = __float2bfloat16(x);
        g_b1hi[n * 128 + k] = h;
        g_b1lo[n * 128 + k] = __float2bfloat16(x - __bfloat162float(h));
    } else if (i < n1 + HID * HID) {    // W2 [256][256]
        int j = i - n1;
        int k = j / HID, n = j - k * HID;
        float x = W2[j];
        __nv_bfloat16 h = __float2bfloat16(x);
        g_b2hi[n * HID + k] = h;
        g_b2lo[n * HID + k] = __float2bfloat16(x - __bfloat162float(h));
    }
}

// ================= bf16 mma.sync GEMM with fused attention logits =================
__device__ __forceinline__ void mma_bf16(float* c, const uint32_t* a, uint32_t b0, uint32_t b1) {
    asm volatile("mma.sync.aligned.m16n8k16.row.col.f32.bf16.bf16.f32 "
        "{%0,%1,%2,%3}, {%4,%5,%6,%7}, {%8,%9}, {%0,%1,%2,%3};"
        : "+f"(c[0]), "+f"(c[1]), "+f"(c[2]), "+f"(c[3])
        : "r"(a[0]), "r"(a[1]), "r"(a[2]), "r"(a[3]), "r"(b0), "r"(b1));
}

// C[M,256] = A[M,K] @ B[K,256]; A is fp32 (split on the fly), B = g_b*hi/lo ([n][k]).
// CTA: 128 rows x 128 cols. 8 warps: wm in {0,1}, wn in {0..3} (32 cols = 1 head).
__global__ void __launch_bounds__(256)
gemm_mma_kernel(int layer, int M, const float* __restrict__ A,
                const float* __restrict__ asrc, const float* __restrict__ adst) {
    const int K = layer ? 256 : 128;
    const __nv_bfloat16* __restrict__ bhi = layer ? g_b2hi : g_b1hi;
    const __nv_bfloat16* __restrict__ blo = layer ? g_b2lo : g_b1lo;

    __shared__ __nv_bfloat16 sAhi[128][40];
    __shared__ __nv_bfloat16 sAlo[128][40];
    __shared__ __nv_bfloat16 sBhi[128][40];
    __shared__ __nv_bfloat16 sBlo[128][40];

    const int tid = threadIdx.x, lane = tid & 31, wid = tid >> 5;
    const int wm = wid >> 2, wn = wid & 3;
    const int row0 = blockIdx.x * 128;
    const int n0 = blockIdx.y * 128;
    const int qid = lane >> 2, qlane = lane & 3;

    float c[4][4][4];
    #pragma unroll
    for (int i = 0; i < 4; i++)
        #pragma unroll
        for (int j = 0; j < 4; j++)
            #pragma unroll
            for (int k = 0; k < 4; k++) c[i][j][k] = 0.f;

    const int nkb = K >> 5;
    for (int kb = 0; kb < nkb; kb++) {
        #pragma unroll
        for (int i = 0; i < 4; i++) {
            int idx = tid + 256 * i;         // 0..1023
            int r = idx >> 3, kq = idx & 7;  // row, 4-elem quad
            int gr = row0 + r;
            float4 v = make_float4(0.f, 0.f, 0.f, 0.f);
            if (gr < M) v = *(const float4*)&A[(size_t)gr * K + kb * 32 + kq * 4];
            __nv_bfloat162 h01 = __floats2bfloat162_rn(v.x, v.y);
            __nv_bfloat162 h23 = __floats2bfloat162_rn(v.z, v.w);
            __nv_bfloat162 l01 = __floats2bfloat162_rn(v.x - __low2float(h01),
                                                       v.y - __high2float(h01));
            __nv_bfloat162 l23 = __floats2bfloat162_rn(v.z - __low2float(h23),
                                                       v.w - __high2float(h23));
            *(uint2*)&sAhi[r][kq * 4] = make_uint2(*(uint32_t*)&h01, *(uint32_t*)&h23);
            *(uint2*)&sAlo[r][kq * 4] = make_uint2(*(uint32_t*)&l01, *(uint32_t*)&l23);
            size_t gb = (size_t)(n0 + r) * K + kb * 32 + kq * 4;
            *(uint2*)&sBhi[r][kq * 4] = *(const uint2*)&bhi[gb];
            *(uint2*)&sBlo[r][kq * 4] = *(const uint2*)&blo[gb];
        }
        __syncthreads();

        #pragma unroll
        for (int ks = 0; ks < 2; ks++) {
            const int k0 = ks * 16;
            uint32_t ah[4][4], al[4][4];
            #pragma unroll
            for (int mi = 0; mi < 4; mi++) {
                int r = wm * 64 + mi * 16 + qid;
                int cw = k0 + qlane * 2;
                ah[mi][0] = *(const uint32_t*)&sAhi[r][cw];
                ah[mi][1] = *(const uint32_t*)&sAhi[r + 8][cw];
                ah[mi][2] = *(const uint32_t*)&sAhi[r][cw + 8];
                ah[mi][3] = *(const uint32_t*)&sAhi[r + 8][cw + 8];
                al[mi][0] = *(const uint32_t*)&sAlo[r][cw];
                al[mi][1] = *(const uint32_t*)&sAlo[r + 8][cw];
                al[mi][2] = *(const uint32_t*)&sAlo[r][cw + 8];
                al[mi][3] = *(const uint32_t*)&sAlo[r + 8][cw + 8];
            }
            #pragma unroll
            for (int ni = 0; ni < 4; ni++) {
                int n = wn * 32 + ni * 8 + qid;
                int kw = k0 + qlane * 2;
                uint32_t bh0 = *(const uint32_t*)&sBhi[n][kw];
                uint32_t bh1 = *(const uint32_t*)&sBhi[n][kw + 8];
                uint32_t bl0 = *(const uint32_t*)&sBlo[n][kw];
                uint32_t bl1 = *(const uint32_t*)&sBlo[n][kw + 8];
                #pragma unroll
                for (int mi = 0; mi < 4; mi++) {
                    mma_bf16(c[mi][ni], ah[mi], bh0, bh1);
                    mma_bf16(c[mi][ni], ah[mi], bl0, bl1);
                    mma_bf16(c[mi][ni], al[mi], bh0, bh1);
                }
            }
        }
        __syncthreads();
    }

    // ---- fused attention logits (this warp's 32 cols == one head) ----
    const int head = (n0 >> 5) + wn;
    float as_v[4][2], ad_v[4][2];
    #pragma unroll
    for (int ni = 0; ni < 4; ni++)
        #pragma unroll
        for (int j = 0; j < 2; j++) {
            int col = head * 32 + ni * 8 + qlane * 2 + j;
            as_v[ni][j] = asrc[col];
            ad_v[ni][j] = adst[col];
        }
    #pragma unroll
    for (int mi = 0; mi < 4; mi++) {
        #pragma unroll
        for (int h = 0; h < 2; h++) {
            float ps = 0.f, pd = 0.f;
            #pragma unroll
            for (int ni = 0; ni < 4; ni++)
                #pragma unroll
                for (int j = 0; j < 2; j++) {
                    float v = c[mi][ni][h * 2 + j];
                    ps = fmaf(v, as_v[ni][j], ps);
                    pd = fmaf(v, ad_v[ni][j], pd);
                }
            ps += __shfl_xor_sync(0xffffffffu, ps, 1);
            ps += __shfl_xor_sync(0xffffffffu, ps, 2);
            pd += __shfl_xor_sync(0xffffffffu, pd, 1);
            pd += __shfl_xor_sync(0xffffffffu, pd, 2);
            int row = row0 + wm * 64 + mi * 16 + h * 8 + qid;
            if (qlane == 0 && row < M) {
                g_als[row * NHEAD + head] = ps;
                g_ald[row * NHEAD + head] = pd;
            }
        }
    }
    // ---- store C ----
    #pragma unroll
    for (int mi = 0; mi < 4; mi++) {
        int r = row0 + wm * 64 + mi * 16 + qid;
        #pragma unroll
        for (int ni = 0; ni < 4; ni++) {
            int cg = n0 + wn * 32 + ni * 8 + qlane * 2;
            if (r < M)
                *(float2*)&g_h[(size_t)r * HID + cg] = make_float2(c[mi][ni][0], c[mi][ni][1]);
            if (r + 8 < M)
                *(float2*)&g_h[(size_t)(r + 8) * HID + cg] = make_float2(c[mi][ni][2], c[mi][ni][3]);
        }
    }
}

// ================= segmented softmax + aggregation + bias + ELU =================
// No max subtraction: exp(e)/sum(exp(e)) is mathematically identical and logits are O(3).
__global__ void __launch_bounds__(256)
gat_agg_kernel(const float* __restrict__ bias, float* __restrict__ outp) {
    int v = blockIdx.x;
    int tid = threadIdx.x, lane = tid & 31, warp = tid >> 5;
    int start = g_rowptr[v], end = g_rowptr[v + 1];

    __shared__ float sh_s[8];
    __shared__ float sh_w[8][32];
    __shared__ int   sh_src[32];
    __shared__ float4 sh_red[256];

    float aldv = g_ald[v * NHEAD + warp];

    float ssum = 0.f;
    float4 acc = make_float4(0.f, 0.f, 0.f, 0.f);
    int cg = tid & 63;          // 64 channel-groups of 4 channels
    int sub = tid >> 6;         // 4 concurrent edge sub-streams
    int headc = cg >> 3;        // head owning these channels

    for (int t = start; t < end; t += 32) {
        int cnt = min(32, end - t);
        if (lane < cnt) {
            int s = g_srcs[t + lane];
            if (warp == 0) sh_src[lane] = s;
            float e = g_als[s * NHEAD + warp] + aldv;
            e = (e > 0.f) ? e : 0.2f * e;
            float w = __expf(e);
            sh_w[warp][lane] = w;
            ssum += w;
        }
        __syncthreads();
        for (int j = sub; j < cnt; j += 4) {
            int s = sh_src[j];
            float w = sh_w[headc][j];
            const float4 hv = *reinterpret_cast<const float4*>(&g_h[(size_t)s * HID + cg * 4]);
            acc.x = fmaf(w, hv.x, acc.x);
            acc.y = fmaf(w, hv.y, acc.y);
            acc.z = fmaf(w, hv.z, acc.z);
            acc.w = fmaf(w, hv.w, acc.w);
        }
        __syncthreads();
    }

    #pragma unroll
    for (int o = 16; o; o >>= 1) ssum += __shfl_xor_sync(0xffffffffu, ssum, o);
    if (lane == 0) sh_s[warp] = ssum;

    sh_red[tid] = acc;
    __syncthreads();

    if (tid < 64) {
        float4 a0 = sh_red[tid];
        float4 a1 = sh_red[tid + 64];
        float4 a2 = sh_red[tid + 128];
        float4 a3 = sh_red[tid + 192];
        float r0 = a0.x + a1.x + a2.x + a3.x;
        float r1 = a0.y + a1.y + a2.y + a3.y;
        float r2 = a0.z + a1.z + a2.z + a3.z;
        float r3 = a0.w + a1.w + a2.w + a3.w;
        float inv = 1.f / (sh_s[tid >> 3] + 1e-16f);
        float vals[4] = { r0 * inv, r1 * inv, r2 * inv, r3 * inv };
        #pragma unroll
        for (int k = 0; k < 4; k++) {
            float val = vals[k] + bias[tid * 4 + k];
            val = (val > 0.f) ? val : (__expf(val) - 1.f);   // ELU
            outp[(size_t)v * HID + tid * 4 + k] = val;
        }
    }
}

// ================= driver =================
extern "C" void kernel_launch(void* const* d_in, const int* in_sizes, int n_in,
                              void* d_out, int out_size) {
    const float* x    = (const float*)d_in[0];
    const int*   ei   = (const int*)d_in[1];
    const float* W1   = (const float*)d_in[2];
    const float* a1s  = (const float*)d_in[3];
    const float* a1d  = (const float*)d_in[4];
    const float* b1   = (const float*)d_in[5];
    const float* W2   = (const float*)d_in[6];
    const float* a2s  = (const float*)d_in[7];
    const float* a2d  = (const float*)d_in[8];
    const float* b2   = (const float*)d_in[9];
    float* out = (float*)d_out;

    int etot = in_sizes[1] / 2;
    const int* src = ei;
    const int* dst = ei + etot;
    int eb4 = (etot / 4 + 255) / 256 + 1;

    // CSR by dst
    zero_counts_kernel<<<(NNODES + 256) / 256, 256>>>();
    hist_kernel<<<eb4, 256>>>(dst, etot);
    scan_local_kernel<<<SCAN_NB, 256>>>();
    scan_bsums_kernel<<<1, 256>>>();
    scan_add_kernel<<<SCAN_NB, 256>>>();
    scatter_kernel<<<eb4, 256>>>(src, dst, etot);

    // weight splits (both layers)
    convW_kernel<<<(128 * HID + HID * HID + 255) / 256, 256>>>(W1, W2);

    dim3 ggrid((NNODES + 127) / 128, 2);

    // layer 1
    gemm_mma_kernel<<<ggrid, 256>>>(0, NNODES, x, a1s, a1d);
    gat_agg_kernel<<<NNODES, 256>>>(b1, g_x1);

    // layer 2
    gemm_mma_kernel<<<ggrid, 256>>>(1, NNODES, g_x1, a2s, a2d);
    gat_agg_kernel<<<NNODES, 256>>>(b2, out);
}

// round 7
// speedup vs baseline: 3.0021x; 3.0021x over previous
#include <cuda_runtime.h>
#include <cuda_bf16.h>
#include <cstdint>

#define NNODES   50000
#define ETOT_MAX 900000
#define HID      256
#define NHEAD    8
#define SCAN_NB  196          // 196*256 = 50176 >= NNODES

// ================= scratch (static device globals) =================
__device__ int   g_rowptr[NNODES + 1];
__device__ int   g_cursor[NNODES];
__device__ int   g_scantmp[NNODES];
__device__ int   g_bsum[256];
__device__ int   g_srcs[ETOT_MAX];
__device__ __align__(16) float g_h[NNODES * HID];    // transformed features (current layer)
__device__ __align__(16) float g_x1[NNODES * HID];   // layer-1 output
__device__ float g_als[NNODES * NHEAD];
__device__ float g_ald[NNODES * NHEAD];
// bf16 hi/lo split weights, stored [n][k]
__device__ __align__(16) __nv_bfloat16 g_b1hi[HID * 128];
__device__ __align__(16) __nv_bfloat16 g_b1lo[HID * 128];
__device__ __align__(16) __nv_bfloat16 g_b2hi[HID * HID];
__device__ __align__(16) __nv_bfloat16 g_b2lo[HID * HID];

// ================= CSR build =================
__global__ void zero_counts_kernel() {
    int i = blockIdx.x * blockDim.x + threadIdx.x;
    if (i <= NNODES) g_rowptr[i] = 0;
}

__global__ void hist_kernel(const int* __restrict__ dst, int etot) {
    int i = blockIdx.x * blockDim.x + threadIdx.x;
    int n4 = etot >> 2;
    if (i < n4) {
        int4 d = ((const int4*)dst)[i];
        atomicAdd(&g_rowptr[d.x], 1);
        atomicAdd(&g_rowptr[d.y], 1);
        atomicAdd(&g_rowptr[d.z], 1);
        atomicAdd(&g_rowptr[d.w], 1);
    }
    int rem = etot - n4 * 4;
    if (i < rem) atomicAdd(&g_rowptr[dst[n4 * 4 + i]], 1);
}

// two-level scan
__global__ void scan_local_kernel() {
    int t = threadIdx.x, i = blockIdx.x * 256 + t;
    int lane = t & 31, wid = t >> 5;
    int val = (i < NNODES) ? g_rowptr[i] : 0;
    int x = val;
    #pragma unroll
    for (int o = 1; o < 32; o <<= 1) {
        int y = __shfl_up_sync(0xffffffffu, x, o);
        if (lane >= o) x += y;
    }
    __shared__ int wsum[8];
    if (lane == 31) wsum[wid] = x;
    __syncthreads();
    if (t < 8) {
        int s = wsum[t];
        #pragma unroll
        for (int o = 1; o < 8; o <<= 1) {
            int y = __shfl_up_sync(0xffu, s, o);
            if (t >= o) s += y;
        }
        wsum[t] = s;
    }
    __syncthreads();
    int incl = x + (wid ? wsum[wid - 1] : 0);
    if (i < NNODES) g_scantmp[i] = incl - val;
    if (t == 255) g_bsum[blockIdx.x] = incl;
}

__global__ void scan_bsums_kernel() {
    int t = threadIdx.x;
    int lane = t & 31, wid = t >> 5;
    int val = (t < SCAN_NB) ? g_bsum[t] : 0;
    int x = val;
    #pragma unroll
    for (int o = 1; o < 32; o <<= 1) {
        int y = __shfl_up_sync(0xffffffffu, x, o);
        if (lane >= o) x += y;
    }
    __shared__ int wsum[8];
    if (lane == 31) wsum[wid] = x;
    __syncthreads();
    if (t < 8) {
        int s = wsum[t];
        #pragma unroll
        for (int o = 1; o < 8; o <<= 1) {
            int y = __shfl_up_sync(0xffu, s, o);
            if (t >= o) s += y;
        }
        wsum[t] = s;
    }
    __syncthreads();
    int incl = x + (wid ? wsum[wid - 1] : 0);
    if (t < SCAN_NB) g_bsum[t] = incl - val;
    if (t == 255) g_rowptr[NNODES] = incl;
}

__global__ void scan_add_kernel() {
    int i = blockIdx.x * 256 + threadIdx.x;
    if (i < NNODES) {
        int e = g_scantmp[i] + g_bsum[blockIdx.x];
        g_rowptr[i] = e;
        g_cursor[i] = e;
    }
}

__global__ void scatter_kernel(const int* __restrict__ src,
                               const int* __restrict__ dst, int etot) {
    int i = blockIdx.x * blockDim.x + threadIdx.x;
    int n4 = etot >> 2;
    if (i < n4) {
        int4 s = ((const int4*)src)[i];
        int4 d = ((const int4*)dst)[i];
        g_srcs[atomicAdd(&g_cursor[d.x], 1)] = s.x;
        g_srcs[atomicAdd(&g_cursor[d.y], 1)] = s.y;
        g_srcs[atomicAdd(&g_cursor[d.z], 1)] = s.z;
        g_srcs[atomicAdd(&g_cursor[d.w], 1)] = s.w;
    }
    int rem = etot - n4 * 4;
    if (i < rem) {
        int j = n4 * 4 + i;
        g_srcs[atomicAdd(&g_cursor[dst[j]], 1)] = src[j];
    }
}

// ================= weight fp32 -> bf16 hi/lo split (both layers, one kernel) =================
__global__ void convW_kernel(const float* __restrict__ W1, const float* __restrict__ W2) {
    int i = blockIdx.x * blockDim.x + threadIdx.x;
    const int n1 = 128 * HID;
    if (i < n1) {                       // W1 [128][256]
        int k = i / HID, n = i - k * HID;
        float x = W1[i];
        __nv_bfloat16 h = __float2bfloat16(x);
        g_b1hi[n * 128 + k] = h;
        g_b1lo[n * 128 + k] = __float2bfloat16(x - __bfloat162float(h));
    } else if (i < n1 + HID * HID) {    // W2 [256][256]
        int j = i - n1;
        int k = j / HID, n = j - k * HID;
        float x = W2[j];
        __nv_bfloat16 h = __float2bfloat16(x);
        g_b2hi[n * HID + k] = h;
        g_b2lo[n * HID + k] = __float2bfloat16(x - __bfloat162float(h));
    }
}

// ================= bf16 mma.sync GEMM with fused attention logits =================
__device__ __forceinline__ void mma_bf16(float* c, const uint32_t* a, uint32_t b0, uint32_t b1) {
    asm volatile("mma.sync.aligned.m16n8k16.row.col.f32.bf16.bf16.f32 "
        "{%0,%1,%2,%3}, {%4,%5,%6,%7}, {%8,%9}, {%0,%1,%2,%3};"
        : "+f"(c[0]), "+f"(c[1]), "+f"(c[2]), "+f"(c[3])
        : "r"(a[0]), "r"(a[1]), "r"(a[2]), "r"(a[3]), "r"(b0), "r"(b1));
}

// C[M,256] = A[M,K] @ B[K,256]; A is fp32 (split on the fly), B = g_b*hi/lo ([n][k]).
// layer: 0 -> A = Aext (x input), K=128; 1 -> A = g_x1 (device global, selected HERE), K=256.
// CTA: 128 rows x 128 cols. 8 warps: wm in {0,1}, wn in {0..3} (32 cols = 1 head).
__global__ void __launch_bounds__(256)
gemm_mma_kernel(int layer, int M, const float* __restrict__ Aext,
                const float* __restrict__ asrc, const float* __restrict__ adst) {
    const int K = layer ? 256 : 128;
    const float* __restrict__ A = layer ? g_x1 : Aext;   // device-side select (NOT from host!)
    const __nv_bfloat16* __restrict__ bhi = layer ? g_b2hi : g_b1hi;
    const __nv_bfloat16* __restrict__ blo = layer ? g_b2lo : g_b1lo;

    __shared__ __nv_bfloat16 sAhi[128][40];
    __shared__ __nv_bfloat16 sAlo[128][40];
    __shared__ __nv_bfloat16 sBhi[128][40];
    __shared__ __nv_bfloat16 sBlo[128][40];

    const int tid = threadIdx.x, lane = tid & 31, wid = tid >> 5;
    const int wm = wid >> 2, wn = wid & 3;
    const int row0 = blockIdx.x * 128;
    const int n0 = blockIdx.y * 128;
    const int qid = lane >> 2, qlane = lane & 3;

    float c[4][4][4];
    #pragma unroll
    for (int i = 0; i < 4; i++)
        #pragma unroll
        for (int j = 0; j < 4; j++)
            #pragma unroll
            for (int k = 0; k < 4; k++) c[i][j][k] = 0.f;

    const int nkb = K >> 5;
    for (int kb = 0; kb < nkb; kb++) {
        #pragma unroll
        for (int i = 0; i < 4; i++) {
            int idx = tid + 256 * i;         // 0..1023
            int r = idx >> 3, kq = idx & 7;  // row, 4-elem quad
            int gr = row0 + r;
            float4 v = make_float4(0.f, 0.f, 0.f, 0.f);
            if (gr < M) v = *(const float4*)&A[(size_t)gr * K + kb * 32 + kq * 4];
            __nv_bfloat162 h01 = __floats2bfloat162_rn(v.x, v.y);
            __nv_bfloat162 h23 = __floats2bfloat162_rn(v.z, v.w);
            __nv_bfloat162 l01 = __floats2bfloat162_rn(v.x - __low2float(h01),
                                                       v.y - __high2float(h01));
            __nv_bfloat162 l23 = __floats2bfloat162_rn(v.z - __low2float(h23),
                                                       v.w - __high2float(h23));
            *(uint2*)&sAhi[r][kq * 4] = make_uint2(*(uint32_t*)&h01, *(uint32_t*)&h23);
            *(uint2*)&sAlo[r][kq * 4] = make_uint2(*(uint32_t*)&l01, *(uint32_t*)&l23);
            size_t gb = (size_t)(n0 + r) * K + kb * 32 + kq * 4;
            *(uint2*)&sBhi[r][kq * 4] = *(const uint2*)&bhi[gb];
            *(uint2*)&sBlo[r][kq * 4] = *(const uint2*)&blo[gb];
        }
        __syncthreads();

        #pragma unroll
        for (int ks = 0; ks < 2; ks++) {
            const int k0 = ks * 16;
            uint32_t ah[4][4], al[4][4];
            #pragma unroll
            for (int mi = 0; mi < 4; mi++) {
                int r = wm * 64 + mi * 16 + qid;
                int cw = k0 + qlane * 2;
                ah[mi][0] = *(const uint32_t*)&sAhi[r][cw];
                ah[mi][1] = *(const uint32_t*)&sAhi[r + 8][cw];
                ah[mi][2] = *(const uint32_t*)&sAhi[r][cw + 8];
                ah[mi][3] = *(const uint32_t*)&sAhi[r + 8][cw + 8];
                al[mi][0] = *(const uint32_t*)&sAlo[r][cw];
                al[mi][1] = *(const uint32_t*)&sAlo[r + 8][cw];
                al[mi][2] = *(const uint32_t*)&sAlo[r][cw + 8];
                al[mi][3] = *(const uint32_t*)&sAlo[r + 8][cw + 8];
            }
            #pragma unroll
            for (int ni = 0; ni < 4; ni++) {
                int n = wn * 32 + ni * 8 + qid;
                int kw = k0 + qlane * 2;
                uint32_t bh0 = *(const uint32_t*)&sBhi[n][kw];
                uint32_t bh1 = *(const uint32_t*)&sBhi[n][kw + 8];
                uint32_t bl0 = *(const uint32_t*)&sBlo[n][kw];
                uint32_t bl1 = *(const uint32_t*)&sBlo[n][kw + 8];
                #pragma unroll
                for (int mi = 0; mi < 4; mi++) {
                    mma_bf16(c[mi][ni], ah[mi], bh0, bh1);
                    mma_bf16(c[mi][ni], ah[mi], bl0, bl1);
                    mma_bf16(c[mi][ni], al[mi], bh0, bh1);
                }
            }
        }
        __syncthreads();
    }

    // ---- fused attention logits (this warp's 32 cols == one head) ----
    const int head = (n0 >> 5) + wn;
    float as_v[4][2], ad_v[4][2];
    #pragma unroll
    for (int ni = 0; ni < 4; ni++)
        #pragma unroll
        for (int j = 0; j < 2; j++) {
            int col = head * 32 + ni * 8 + qlane * 2 + j;
            as_v[ni][j] = asrc[col];
            ad_v[ni][j] = adst[col];
        }
    #pragma unroll
    for (int mi = 0; mi < 4; mi++) {
        #pragma unroll
        for (int h = 0; h < 2; h++) {
            float ps = 0.f, pd = 0.f;
            #pragma unroll
            for (int ni = 0; ni < 4; ni++)
                #pragma unroll
                for (int j = 0; j < 2; j++) {
                    float v = c[mi][ni][h * 2 + j];
                    ps = fmaf(v, as_v[ni][j], ps);
                    pd = fmaf(v, ad_v[ni][j], pd);
                }
            ps += __shfl_xor_sync(0xffffffffu, ps, 1);
            ps += __shfl_xor_sync(0xffffffffu, ps, 2);
            pd += __shfl_xor_sync(0xffffffffu, pd, 1);
            pd += __shfl_xor_sync(0xffffffffu, pd, 2);
            int row = row0 + wm * 64 + mi * 16 + h * 8 + qid;
            if (qlane == 0 && row < M) {
                g_als[row * NHEAD + head] = ps;
                g_ald[row * NHEAD + head] = pd;
            }
        }
    }
    // ---- store C ----
    #pragma unroll
    for (int mi = 0; mi < 4; mi++) {
        int r = row0 + wm * 64 + mi * 16 + qid;
        #pragma unroll
        for (int ni = 0; ni < 4; ni++) {
            int cg = n0 + wn * 32 + ni * 8 + qlane * 2;
            if (r < M)
                *(float2*)&g_h[(size_t)r * HID + cg] = make_float2(c[mi][ni][0], c[mi][ni][1]);
            if (r + 8 < M)
                *(float2*)&g_h[(size_t)(r + 8) * HID + cg] = make_float2(c[mi][ni][2], c[mi][ni][3]);
        }
    }
}

// ================= segmented softmax + aggregation + bias + ELU =================
// No max subtraction: exp(e)/sum(exp(e)) is mathematically identical; logits are O(3).
// use_internal: 1 -> write g_x1 (selected device-side), 0 -> write outp (d_out).
__global__ void __launch_bounds__(256)
gat_agg_kernel(const float* __restrict__ bias, float* __restrict__ outp,
               int use_internal) {
    int v = blockIdx.x;
    int tid = threadIdx.x, lane = tid & 31, warp = tid >> 5;
    int start = g_rowptr[v], end = g_rowptr[v + 1];

    __shared__ float sh_s[8];
    __shared__ float sh_w[8][32];
    __shared__ int   sh_src[32];
    __shared__ float4 sh_red[256];

    float aldv = g_ald[v * NHEAD + warp];

    float ssum = 0.f;
    float4 acc = make_float4(0.f, 0.f, 0.f, 0.f);
    int cg = tid & 63;          // 64 channel-groups of 4 channels
    int sub = tid >> 6;         // 4 concurrent edge sub-streams
    int headc = cg >> 3;        // head owning these channels

    for (int t = start; t < end; t += 32) {
        int cnt = min(32, end - t);
        if (lane < cnt) {
            int s = g_srcs[t + lane];
            if (warp == 0) sh_src[lane] = s;
            float e = g_als[s * NHEAD + warp] + aldv;
            e = (e > 0.f) ? e : 0.2f * e;
            float w = __expf(e);
            sh_w[warp][lane] = w;
            ssum += w;
        }
        __syncthreads();
        for (int j = sub; j < cnt; j += 4) {
            int s = sh_src[j];
            float w = sh_w[headc][j];
            const float4 hv = *reinterpret_cast<const float4*>(&g_h[(size_t)s * HID + cg * 4]);
            acc.x = fmaf(w, hv.x, acc.x);
            acc.y = fmaf(w, hv.y, acc.y);
            acc.z = fmaf(w, hv.z, acc.z);
            acc.w = fmaf(w, hv.w, acc.w);
        }
        __syncthreads();
    }

    #pragma unroll
    for (int o = 16; o; o >>= 1) ssum += __shfl_xor_sync(0xffffffffu, ssum, o);
    if (lane == 0) sh_s[warp] = ssum;

    sh_red[tid] = acc;
    __syncthreads();

    if (tid < 64) {
        float4 a0 = sh_red[tid];
        float4 a1 = sh_red[tid + 64];
        float4 a2 = sh_red[tid + 128];
        float4 a3 = sh_red[tid + 192];
        float r0 = a0.x + a1.x + a2.x + a3.x;
        float r1 = a0.y + a1.y + a2.y + a3.y;
        float r2 = a0.z + a1.z + a2.z + a3.z;
        float r3 = a0.w + a1.w + a2.w + a3.w;
        float inv = 1.f / (sh_s[tid >> 3] + 1e-16f);
        float vals[4] = { r0 * inv, r1 * inv, r2 * inv, r3 * inv };
        float* dstp = use_internal ? (g_x1 + (size_t)v * HID) : (outp + (size_t)v * HID);
        #pragma unroll
        for (int k = 0; k < 4; k++) {
            float val = vals[k] + bias[tid * 4 + k];
            val = (val > 0.f) ? val : (__expf(val) - 1.f);   // ELU
            dstp[tid * 4 + k] = val;
        }
    }
}

// ================= driver =================
extern "C" void kernel_launch(void* const* d_in, const int* in_sizes, int n_in,
                              void* d_out, int out_size) {
    const float* x    = (const float*)d_in[0];
    const int*   ei   = (const int*)d_in[1];
    const float* W1   = (const float*)d_in[2];
    const float* a1s  = (const float*)d_in[3];
    const float* a1d  = (const float*)d_in[4];
    const float* b1   = (const float*)d_in[5];
    const float* W2   = (const float*)d_in[6];
    const float* a2s  = (const float*)d_in[7];
    const float* a2d  = (const float*)d_in[8];
    const float* b2   = (const float*)d_in[9];
    float* out = (float*)d_out;

    int etot = in_sizes[1] / 2;
    const int* src = ei;
    const int* dst = ei + etot;
    int eb4 = (etot / 4 + 255) / 256 + 1;

    // CSR by dst
    zero_counts_kernel<<<(NNODES + 256) / 256, 256>>>();
    hist_kernel<<<eb4, 256>>>(dst, etot);
    scan_local_kernel<<<SCAN_NB, 256>>>();
    scan_bsums_kernel<<<1, 256>>>();
    scan_add_kernel<<<SCAN_NB, 256>>>();
    scatter_kernel<<<eb4, 256>>>(src, dst, etot);

    // weight splits (both layers)
    convW_kernel<<<(128 * HID + HID * HID + 255) / 256, 256>>>(W1, W2);

    dim3 ggrid((NNODES + 127) / 128, 2);

    // layer 1
    gemm_mma_kernel<<<ggrid, 256>>>(0, NNODES, x, a1s, a1d);
    gat_agg_kernel<<<NNODES, 256>>>(b1, nullptr, 1);

    // layer 2 (A = g_x1, selected inside the kernel)
    gemm_mma_kernel<<<ggrid, 256>>>(1, NNODES, nullptr, a2s, a2d);
    gat_agg_kernel<<<NNODES, 256>>>(b2, out, 0);
}

// round 8
// speedup vs baseline: 3.1059x; 1.0346x over previous
#include <cuda_runtime.h>
#include <cuda_bf16.h>
#include <cstdint>

#define NNODES   50000
#define ETOT_MAX 900000
#define HID      256
#define NHEAD    8
#define SCAN_NB  196          // 196*256 = 50176 >= NNODES

// ================= scratch (static device globals) =================
__device__ int   g_rowptr[NNODES + 1];
__device__ int   g_cursor[NNODES];
__device__ int   g_scantmp[NNODES];
__device__ int   g_bsum[256];
__device__ int   g_srcs[ETOT_MAX];
__device__ __align__(16) float g_h[NNODES * HID];    // transformed features (current layer)
__device__ __align__(16) float g_x1[NNODES * HID];   // layer-1 output
__device__ float g_als[NNODES * NHEAD];
__device__ float g_ald[NNODES * NHEAD];
// bf16 hi/lo split weights, stored [n][k]
__device__ __align__(16) __nv_bfloat16 g_b1hi[HID * 128];
__device__ __align__(16) __nv_bfloat16 g_b1lo[HID * 128];
__device__ __align__(16) __nv_bfloat16 g_b2hi[HID * HID];
__device__ __align__(16) __nv_bfloat16 g_b2lo[HID * HID];

// ================= CSR build =================
__global__ void zero_counts_kernel() {
    int i = blockIdx.x * blockDim.x + threadIdx.x;
    if (i <= NNODES) g_rowptr[i] = 0;
}

__global__ void hist_kernel(const int* __restrict__ dst, int etot) {
    int i = blockIdx.x * blockDim.x + threadIdx.x;
    int n4 = etot >> 2;
    if (i < n4) {
        int4 d = ((const int4*)dst)[i];
        atomicAdd(&g_rowptr[d.x], 1);
        atomicAdd(&g_rowptr[d.y], 1);
        atomicAdd(&g_rowptr[d.z], 1);
        atomicAdd(&g_rowptr[d.w], 1);
    }
    int rem = etot - n4 * 4;
    if (i < rem) atomicAdd(&g_rowptr[dst[n4 * 4 + i]], 1);
}

// two-level scan
__global__ void scan_local_kernel() {
    int t = threadIdx.x, i = blockIdx.x * 256 + t;
    int lane = t & 31, wid = t >> 5;
    int val = (i < NNODES) ? g_rowptr[i] : 0;
    int x = val;
    #pragma unroll
    for (int o = 1; o < 32; o <<= 1) {
        int y = __shfl_up_sync(0xffffffffu, x, o);
        if (lane >= o) x += y;
    }
    __shared__ int wsum[8];
    if (lane == 31) wsum[wid] = x;
    __syncthreads();
    if (t < 8) {
        int s = wsum[t];
        #pragma unroll
        for (int o = 1; o < 8; o <<= 1) {
            int y = __shfl_up_sync(0xffu, s, o);
            if (t >= o) s += y;
        }
        wsum[t] = s;
    }
    __syncthreads();
    int incl = x + (wid ? wsum[wid - 1] : 0);
    if (i < NNODES) g_scantmp[i] = incl - val;
    if (t == 255) g_bsum[blockIdx.x] = incl;
}

__global__ void scan_bsums_kernel() {
    int t = threadIdx.x;
    int lane = t & 31, wid = t >> 5;
    int val = (t < SCAN_NB) ? g_bsum[t] : 0;
    int x = val;
    #pragma unroll
    for (int o = 1; o < 32; o <<= 1) {
        int y = __shfl_up_sync(0xffffffffu, x, o);
        if (lane >= o) x += y;
    }
    __shared__ int wsum[8];
    if (lane == 31) wsum[wid] = x;
    __syncthreads();
    if (t < 8) {
        int s = wsum[t];
        #pragma unroll
        for (int o = 1; o < 8; o <<= 1) {
            int y = __shfl_up_sync(0xffu, s, o);
            if (t >= o) s += y;
        }
        wsum[t] = s;
    }
    __syncthreads();
    int incl = x + (wid ? wsum[wid - 1] : 0);
    if (t < SCAN_NB) g_bsum[t] = incl - val;
    if (t == 255) g_rowptr[NNODES] = incl;
}

__global__ void scan_add_kernel() {
    int i = blockIdx.x * 256 + threadIdx.x;
    if (i < NNODES) {
        int e = g_scantmp[i] + g_bsum[blockIdx.x];
        g_rowptr[i] = e;
        g_cursor[i] = e;
    }
}

__global__ void scatter_kernel(const int* __restrict__ src,
                               const int* __restrict__ dst, int etot) {
    int i = blockIdx.x * blockDim.x + threadIdx.x;
    int n4 = etot >> 2;
    if (i < n4) {
        int4 s = ((const int4*)src)[i];
        int4 d = ((const int4*)dst)[i];
        g_srcs[atomicAdd(&g_cursor[d.x], 1)] = s.x;
        g_srcs[atomicAdd(&g_cursor[d.y], 1)] = s.y;
        g_srcs[atomicAdd(&g_cursor[d.z], 1)] = s.z;
        g_srcs[atomicAdd(&g_cursor[d.w], 1)] = s.w;
    }
    int rem = etot - n4 * 4;
    if (i < rem) {
        int j = n4 * 4 + i;
        g_srcs[atomicAdd(&g_cursor[dst[j]], 1)] = src[j];
    }
}

// ================= weight fp32 -> bf16 hi/lo split (both layers, one kernel) =================
__global__ void convW_kernel(const float* __restrict__ W1, const float* __restrict__ W2) {
    int i = blockIdx.x * blockDim.x + threadIdx.x;
    const int n1 = 128 * HID;
    if (i < n1) {                       // W1 [128][256]
        int k = i / HID, n = i - k * HID;
        float x = W1[i];
        __nv_bfloat16 h = __float2bfloat16(x);
        g_b1hi[n * 128 + k] = h;
        g_b1lo[n * 128 + k] = __float2bfloat16(x - __bfloat162float(h));
    } else if (i < n1 + HID * HID) {    // W2 [256][256]
        int j = i - n1;
        int k = j / HID, n = j - k * HID;
        float x = W2[j];
        __nv_bfloat16 h = __float2bfloat16(x);
        g_b2hi[n * HID + k] = h;
        g_b2lo[n * HID + k] = __float2bfloat16(x - __bfloat162float(h));
    }
}

// ================= bf16 mma.sync GEMM with fused attention logits =================
__device__ __forceinline__ void mma_bf16(float* c, const uint32_t* a, uint32_t b0, uint32_t b1) {
    asm volatile("mma.sync.aligned.m16n8k16.row.col.f32.bf16.bf16.f32 "
        "{%0,%1,%2,%3}, {%4,%5,%6,%7}, {%8,%9}, {%0,%1,%2,%3};"
        : "+f"(c[0]), "+f"(c[1]), "+f"(c[2]), "+f"(c[3])
        : "r"(a[0]), "r"(a[1]), "r"(a[2]), "r"(a[3]), "r"(b0), "r"(b1));
}

// C[M,256] = A[M,K] @ B[K,256]; A is fp32 (split on the fly), B = g_b*hi/lo ([n][k]).
// layer: 0 -> A = Aext (x input), K=128; 1 -> A = g_x1 (device global, selected HERE), K=256.
// CTA: 128 rows x 128 cols. 8 warps: wm in {0,1}, wn in {0..3} (32 cols = 1 head).
__global__ void __launch_bounds__(256)
gemm_mma_kernel(int layer, int M, const float* __restrict__ Aext,
                const float* __restrict__ asrc, const float* __restrict__ adst) {
    const int K = layer ? 256 : 128;
    const float* __restrict__ A = layer ? g_x1 : Aext;   // device-side select (NOT from host!)
    const __nv_bfloat16* __restrict__ bhi = layer ? g_b2hi : g_b1hi;
    const __nv_bfloat16* __restrict__ blo = layer ? g_b2lo : g_b1lo;

    __shared__ __nv_bfloat16 sAhi[128][40];
    __shared__ __nv_bfloat16 sAlo[128][40];
    __shared__ __nv_bfloat16 sBhi[128][40];
    __shared__ __nv_bfloat16 sBlo[128][40];

    const int tid = threadIdx.x, lane = tid & 31, wid = tid >> 5;
    const int wm = wid >> 2, wn = wid & 3;
    const int row0 = blockIdx.x * 128;
    const int n0 = blockIdx.y * 128;
    const int qid = lane >> 2, qlane = lane & 3;

    float c[4][4][4];
    #pragma unroll
    for (int i = 0; i < 4; i++)
        #pragma unroll
        for (int j = 0; j < 4; j++)
            #pragma unroll
            for (int k = 0; k < 4; k++) c[i][j][k] = 0.f;

    const int nkb = K >> 5;
    for (int kb = 0; kb < nkb; kb++) {
        #pragma unroll
        for (int i = 0; i < 4; i++) {
            int idx = tid + 256 * i;         // 0..1023
            int r = idx >> 3, kq = idx & 7;  // row, 4-elem quad
            int gr = row0 + r;
            float4 v = make_float4(0.f, 0.f, 0.f, 0.f);
            if (gr < M) v = *(const float4*)&A[(size_t)gr * K + kb * 32 + kq * 4];
            __nv_bfloat162 h01 = __floats2bfloat162_rn(v.x, v.y);
            __nv_bfloat162 h23 = __floats2bfloat162_rn(v.z, v.w);
            __nv_bfloat162 l01 = __floats2bfloat162_rn(v.x - __low2float(h01),
                                                       v.y - __high2float(h01));
            __nv_bfloat162 l23 = __floats2bfloat162_rn(v.z - __low2float(h23),
                                                       v.w - __high2float(h23));
            *(uint2*)&sAhi[r][kq * 4] = make_uint2(*(uint32_t*)&h01, *(uint32_t*)&h23);
            *(uint2*)&sAlo[r][kq * 4] = make_uint2(*(uint32_t*)&l01, *(uint32_t*)&l23);
            size_t gb = (size_t)(n0 + r) * K + kb * 32 + kq * 4;
            *(uint2*)&sBhi[r][kq * 4] = *(const uint2*)&bhi[gb];
            *(uint2*)&sBlo[r][kq * 4] = *(const uint2*)&blo[gb];
        }
        __syncthreads();

        #pragma unroll
        for (int ks = 0; ks < 2; ks++) {
            const int k0 = ks * 16;
            uint32_t ah[4][4], al[4][4];
            #pragma unroll
            for (int mi = 0; mi < 4; mi++) {
                int r = wm * 64 + mi * 16 + qid;
                int cw = k0 + qlane * 2;
                ah[mi][0] = *(const uint32_t*)&sAhi[r][cw];
                ah[mi][1] = *(const uint32_t*)&sAhi[r + 8][cw];
                ah[mi][2] = *(const uint32_t*)&sAhi[r][cw + 8];
                ah[mi][3] = *(const uint32_t*)&sAhi[r + 8][cw + 8];
                al[mi][0] = *(const uint32_t*)&sAlo[r][cw];
                al[mi][1] = *(const uint32_t*)&sAlo[r + 8][cw];
                al[mi][2] = *(const uint32_t*)&sAlo[r][cw + 8];
                al[mi][3] = *(const uint32_t*)&sAlo[r + 8][cw + 8];
            }
            #pragma unroll
            for (int ni = 0; ni < 4; ni++) {
                int n = wn * 32 + ni * 8 + qid;
                int kw = k0 + qlane * 2;
                uint32_t bh0 = *(const uint32_t*)&sBhi[n][kw];
                uint32_t bh1 = *(const uint32_t*)&sBhi[n][kw + 8];
                uint32_t bl0 = *(const uint32_t*)&sBlo[n][kw];
                uint32_t bl1 = *(const uint32_t*)&sBlo[n][kw + 8];
                #pragma unroll
                for (int mi = 0; mi < 4; mi++) {
                    mma_bf16(c[mi][ni], ah[mi], bh0, bh1);
                    mma_bf16(c[mi][ni], ah[mi], bl0, bl1);
                    mma_bf16(c[mi][ni], al[mi], bh0, bh1);
                }
            }
        }
        __syncthreads();
    }

    // ---- fused attention logits (this warp's 32 cols == one head) ----
    const int head = (n0 >> 5) + wn;
    float as_v[4][2], ad_v[4][2];
    #pragma unroll
    for (int ni = 0; ni < 4; ni++)
        #pragma unroll
        for (int j = 0; j < 2; j++) {
            int col = head * 32 + ni * 8 + qlane * 2 + j;
            as_v[ni][j] = asrc[col];
            ad_v[ni][j] = adst[col];
        }
    #pragma unroll
    for (int mi = 0; mi < 4; mi++) {
        #pragma unroll
        for (int h = 0; h < 2; h++) {
            float ps = 0.f, pd = 0.f;
            #pragma unroll
            for (int ni = 0; ni < 4; ni++)
                #pragma unroll
                for (int j = 0; j < 2; j++) {
                    float v = c[mi][ni][h * 2 + j];
                    ps = fmaf(v, as_v[ni][j], ps);
                    pd = fmaf(v, ad_v[ni][j], pd);
                }
            ps += __shfl_xor_sync(0xffffffffu, ps, 1);
            ps += __shfl_xor_sync(0xffffffffu, ps, 2);
            pd += __shfl_xor_sync(0xffffffffu, pd, 1);
            pd += __shfl_xor_sync(0xffffffffu, pd, 2);
            int row = row0 + wm * 64 + mi * 16 + h * 8 + qid;
            if (qlane == 0 && row < M) {
                g_als[row * NHEAD + head] = ps;
                g_ald[row * NHEAD + head] = pd;
            }
        }
    }
    // ---- store C ----
    #pragma unroll
    for (int mi = 0; mi < 4; mi++) {
        int r = row0 + wm * 64 + mi * 16 + qid;
        #pragma unroll
        for (int ni = 0; ni < 4; ni++) {
            int cg = n0 + wn * 32 + ni * 8 + qlane * 2;
            if (r < M)
                *(float2*)&g_h[(size_t)r * HID + cg] = make_float2(c[mi][ni][0], c[mi][ni][1]);
            if (r + 8 < M)
                *(float2*)&g_h[(size_t)(r + 8) * HID + cg] = make_float2(c[mi][ni][2], c[mi][ni][3]);
        }
    }
}

// ================= segmented softmax + aggregation + bias + ELU =================
// No max subtraction: exp(e)/sum(exp(e)) is mathematically identical; logits are O(3).
// use_internal: 1 -> write g_x1 (selected device-side), 0 -> write outp (d_out).
__global__ void __launch_bounds__(256)
gat_agg_kernel(const float* __restrict__ bias, float* __restrict__ outp,
               int use_internal) {
    int v = blockIdx.x;
    int tid = threadIdx.x, lane = tid & 31, warp = tid >> 5;
    int start = g_rowptr[v], end = g_rowptr[v + 1];

    __shared__ float sh_s[8];
    __shared__ float sh_w[8][32];
    __shared__ int   sh_src[32];
    __shared__ float4 sh_red[256];

    float aldv = g_ald[v * NHEAD + warp];

    float ssum = 0.f;
    float4 acc = make_float4(0.f, 0.f, 0.f, 0.f);
    int cg = tid & 63;          // 64 channel-groups of 4 channels
    int sub = tid >> 6;         // 4 concurrent edge sub-streams
    int headc = cg >> 3;        // head owning these channels

    for (int t = start; t < end; t += 32) {
        int cnt = min(32, end - t);
        if (lane < cnt) {
            int s = g_srcs[t + lane];
            if (warp == 0) sh_src[lane] = s;
            float e = g_als[s * NHEAD + warp] + aldv;
            e = (e > 0.f) ? e : 0.2f * e;
            float w = __expf(e);
            sh_w[warp][lane] = w;
            ssum += w;
        }
        __syncthreads();
        for (int j = sub; j < cnt; j += 4) {
            int s = sh_src[j];
            float w = sh_w[headc][j];
            const float4 hv = *reinterpret_cast<const float4*>(&g_h[(size_t)s * HID + cg * 4]);
            acc.x = fmaf(w, hv.x, acc.x);
            acc.y = fmaf(w, hv.y, acc.y);
            acc.z = fmaf(w, hv.z, acc.z);
            acc.w = fmaf(w, hv.w, acc.w);
        }
        __syncthreads();
    }

    #pragma unroll
    for (int o = 16; o; o >>= 1) ssum += __shfl_xor_sync(0xffffffffu, ssum, o);
    if (lane == 0) sh_s[warp] = ssum;

    sh_red[tid] = acc;
    __syncthreads();

    if (tid < 64) {
        float4 a0 = sh_red[tid];
        float4 a1 = sh_red[tid + 64];
        float4 a2 = sh_red[tid + 128];
        float4 a3 = sh_red[tid + 192];
        float r0 = a0.x + a1.x + a2.x + a3.x;
        float r1 = a0.y + a1.y + a2.y + a3.y;
        float r2 = a0.z + a1.z + a2.z + a3.z;
        float r3 = a0.w + a1.w + a2.w + a3.w;
        float inv = 1.f / (sh_s[tid >> 3] + 1e-16f);
        float vals[4] = { r0 * inv, r1 * inv, r2 * inv, r3 * inv };
        float* dstp = use_internal ? (g_x1 + (size_t)v * HID) : (outp + (size_t)v * HID);
        #pragma unroll
        for (int k = 0; k < 4; k++) {
            float val = vals[k] + bias[tid * 4 + k];
            val = (val > 0.f) ? val : (__expf(val) - 1.f);   // ELU
            dstp[tid * 4 + k] = val;
        }
    }
}

// ================= driver =================
extern "C" void kernel_launch(void* const* d_in, const int* in_sizes, int n_in,
                              void* d_out, int out_size) {
    const float* x    = (const float*)d_in[0];
    const int*   ei   = (const int*)d_in[1];
    const float* W1   = (const float*)d_in[2];
    const float* a1s  = (const float*)d_in[3];
    const float* a1d  = (const float*)d_in[4];
    const float* b1   = (const float*)d_in[5];
    const float* W2   = (const float*)d_in[6];
    const float* a2s  = (const float*)d_in[7];
    const float* a2d  = (const float*)d_in[8];
    const float* b2   = (const float*)d_in[9];
    float* out = (float*)d_out;

    int etot = in_sizes[1] / 2;
    const int* src = ei;
    const int* dst = ei + etot;
    int eb4 = (etot / 4 + 255) / 256 + 1;

    // one-time side-stream/event setup (first call is the uncaptured correctness run)
    static cudaStream_t s_side = nullptr;
    static cudaEvent_t ev_fork = nullptr, ev_join = nullptr;
    if (!s_side) {
        cudaStreamCreateWithFlags(&s_side, cudaStreamNonBlocking);
        cudaEventCreateWithFlags(&ev_fork, cudaEventDisableTiming);
        cudaEventCreateWithFlags(&ev_join, cudaEventDisableTiming);
    }

    // ---- main stream: weight split + layer-1 GEMM (independent of CSR) ----
    convW_kernel<<<(128 * HID + HID * HID + 255) / 256, 256>>>(W1, W2);

    // ---- fork: CSR build on side stream, concurrent with gemm1 ----
    cudaEventRecord(ev_fork, 0);
    cudaStreamWaitEvent(s_side, ev_fork, 0);
    zero_counts_kernel<<<(NNODES + 256) / 256, 256, 0, s_side>>>();
    hist_kernel<<<eb4, 256, 0, s_side>>>(dst, etot);
    scan_local_kernel<<<SCAN_NB, 256, 0, s_side>>>();
    scan_bsums_kernel<<<1, 256, 0, s_side>>>();

    dim3 ggrid((NNODES + 127) / 128, 2);
    gemm_mma_kernel<<<ggrid, 256>>>(0, NNODES, x, a1s, a1d);     // layer-1 GEMM on main

    scan_add_kernel<<<SCAN_NB, 256, 0, s_side>>>();
    scatter_kernel<<<eb4, 256, 0, s_side>>>(src, dst, etot);
    cudaEventRecord(ev_join, s_side);
    cudaStreamWaitEvent(0, ev_join, 0);

    // ---- join: aggregation needs CSR + gemm1 ----
    gat_agg_kernel<<<NNODES, 256>>>(b1, nullptr, 1);

    // layer 2 (A = g_x1, selected inside the kernel)
    gemm_mma_kernel<<<ggrid, 256>>>(1, NNODES, nullptr, a2s, a2d);
    gat_agg_kernel<<<NNODES, 256>>>(b2, out, 0);
}